// round 1
// baseline (speedup 1.0000x reference)
#include <cuda_runtime.h>
#include <math.h>

// Problem constants
#define BB 8
#define TT 4096
#define DD 512
#define OO 512
#define MM (BB*TT)      // 32768 tokens
#define KK 1024         // 2*D (x_{t-1} ++ x_t)
// 3 gates * 512 = 1536 output columns total; handled as gate-selected blocks

// Scan chunking
#define NC 64           // chunks per sequence
#define CL (TT/NC)      // 64 steps per chunk

// ---------------- scratch (device globals; no allocation allowed) ----------
__device__ float g_z[(size_t)MM * OO];   // tanh(conv_z)
__device__ float g_f[(size_t)MM * OO];   // sigmoid(conv_f)
__device__ float g_o[(size_t)MM * OO];   // sigmoid(conv_o)
__device__ float g_cH[BB * NC * OO];     // per-chunk local final h
__device__ float g_cP[BB * NC * OO];     // per-chunk prod(f)
__device__ float g_cIn[BB * NC * OO];    // per-chunk carry-in h

// ---------------- GEMM: gates pre-activation + activation ------------------
// C[i, n] = sum_k A[i,k] * Wsel[k,n_in_gate] + bias, then activation.
// A[i,k] = (k<512) ? (t==0 ? 0 : x[i-1, k]) : x[i, k-512]
// Block tile: 128x128, BK=8, 256 threads, 8x8 per-thread microtile.
__global__ __launch_bounds__(256) void gemm_gates_kernel(
    const float* __restrict__ x,
    const float* __restrict__ Wz, const float* __restrict__ Wf, const float* __restrict__ Wo,
    const float* __restrict__ bz, const float* __restrict__ bf, const float* __restrict__ bo)
{
    __shared__ float As[8][128 + 4];   // padded to break transpose-store conflicts
    __shared__ float Bs[8][128];

    const int tid = threadIdx.x;
    const int m0 = blockIdx.y * 128;
    const int n0 = blockIdx.x * 128;        // 0..1535 in steps of 128
    const int gate = n0 >> 9;               // 0:z 1:f 2:o (tiles never straddle gates)
    const int nInGate = n0 & 511;           // 0,128,256,384

    const float* __restrict__ W    = (gate == 0) ? Wz : (gate == 1 ? Wf : Wo);
    const float* __restrict__ bias = (gate == 0) ? bz : (gate == 1 ? bf : bo);
    float* __restrict__ outb       = (gate == 0) ? g_z : (gate == 1 ? g_f : g_o);

    const int ty = tid >> 4;                // 0..15  -> row group
    const int tx = tid & 15;                // 0..15  -> col group

    // A-load mapping: one float4 per thread per k-tile
    const int arow = tid >> 1;              // 0..127
    const int ac4  = (tid & 1) * 4;         // 0 or 4
    const int gi   = m0 + arow;             // global token row
    const int tloc = gi & (TT - 1);         // position within sequence

    float acc[8][8];
    #pragma unroll
    for (int i = 0; i < 8; i++)
        #pragma unroll
        for (int j = 0; j < 8; j++) acc[i][j] = 0.0f;

    for (int k0 = 0; k0 < KK; k0 += 8) {
        // ---- load A tile (128 rows x 8 cols) ----
        {
            int k = k0 + ac4;
            float4 v;
            if (k < 512) {
                if (tloc == 0) v = make_float4(0.f, 0.f, 0.f, 0.f);
                else           v = *(const float4*)(x + (size_t)(gi - 1) * DD + k);
            } else {
                v = *(const float4*)(x + (size_t)gi * DD + (k - 512));
            }
            As[ac4 + 0][arow] = v.x;
            As[ac4 + 1][arow] = v.y;
            As[ac4 + 2][arow] = v.z;
            As[ac4 + 3][arow] = v.w;
        }
        // ---- load B tile (8 rows x 128 cols), direct from W[w][d][o] ----
        #pragma unroll
        for (int j = 0; j < 4; j++) {
            int e  = tid + j * 256;
            int kr = e >> 7;                // 0..7
            int nc = e & 127;               // 0..127
            int k  = k0 + kr;
            int w  = k >> 9;                // 0 or 1
            int d  = k & 511;
            Bs[kr][nc] = W[(size_t)w * DD * OO + (size_t)d * OO + nInGate + nc];
        }
        __syncthreads();

        #pragma unroll
        for (int kk = 0; kk < 8; kk++) {
            float a[8], b[8];
            #pragma unroll
            for (int i = 0; i < 8; i++) a[i] = As[kk][ty * 8 + i];
            #pragma unroll
            for (int i = 0; i < 8; i++) b[i] = Bs[kk][tx * 8 + i];
            #pragma unroll
            for (int i = 0; i < 8; i++)
                #pragma unroll
                for (int j = 0; j < 8; j++)
                    acc[i][j] = fmaf(a[i], b[j], acc[i][j]);
        }
        __syncthreads();
    }

    // ---- epilogue: bias + activation + store ----
    #pragma unroll
    for (int i = 0; i < 8; i++) {
        int row = m0 + ty * 8 + i;
        #pragma unroll
        for (int j = 0; j < 8; j++) {
            int col = nInGate + tx * 8 + j;          // 0..511 within gate
            float v = acc[i][j] + bias[col];
            float act;
            if (gate == 0) act = tanhf(v);
            else           act = 1.0f / (1.0f + __expf(-v));
            outb[(size_t)row * OO + col] = act;
        }
    }
}

// ---------------- Scan pass A: local chunk scan + f-product ----------------
__global__ __launch_bounds__(256) void scan_passA(void)
{
    int g = blockIdx.x * blockDim.x + threadIdx.x;   // 0 .. B*NC*O-1
    int c     = g & 511;
    int rest  = g >> 9;
    int chunk = rest & (NC - 1);
    int b     = rest >> 6;

    int idx = ((b * TT + chunk * CL) * OO) + c;
    float h = 0.0f, P = 1.0f;
    #pragma unroll 4
    for (int t = 0; t < CL; t++) {
        float f = g_f[idx];
        float z = g_z[idx];
        h = z + f * (h - z);      // f*h + (1-f)*z
        P *= f;
        idx += OO;
    }
    int j = (b * NC + chunk) * OO + c;
    g_cH[j] = h;
    g_cP[j] = P;
}

// ---------------- Scan pass B: sequential combine over chunks --------------
__global__ __launch_bounds__(256) void scan_passB(void)
{
    int g = blockIdx.x * blockDim.x + threadIdx.x;   // 0 .. B*O-1
    int c = g & 511;
    int b = g >> 9;
    float H = 0.0f;
    for (int k = 0; k < NC; k++) {
        int j = (b * NC + k) * OO + c;
        g_cIn[j] = H;                       // carry-in for chunk k
        H = g_cP[j] * H + g_cH[j];
    }
}

// ---------------- Scan pass C: recompute with carry + output gate ----------
__global__ __launch_bounds__(256) void scan_passC(float* __restrict__ out)
{
    int g = blockIdx.x * blockDim.x + threadIdx.x;
    int c     = g & 511;
    int rest  = g >> 9;
    int chunk = rest & (NC - 1);
    int b     = rest >> 6;

    float h = g_cIn[(b * NC + chunk) * OO + c];
    int idx = ((b * TT + chunk * CL) * OO) + c;
    #pragma unroll 4
    for (int t = 0; t < CL; t++) {
        float f = g_f[idx];
        float z = g_z[idx];
        h = z + f * (h - z);
        out[idx] = g_o[idx] * h;
        idx += OO;
    }
}

// ---------------- launch ----------------------------------------------------
extern "C" void kernel_launch(void* const* d_in, const int* in_sizes, int n_in,
                              void* d_out, int out_size)
{
    const float* x  = (const float*)d_in[0];
    const float* Wz = (const float*)d_in[1];
    const float* Wf = (const float*)d_in[2];
    const float* Wo = (const float*)d_in[3];
    const float* bz = (const float*)d_in[4];
    const float* bf = (const float*)d_in[5];
    const float* bo = (const float*)d_in[6];
    float* out = (float*)d_out;

    dim3 ggrid(1536 / 128, MM / 128);   // (12, 256)
    gemm_gates_kernel<<<ggrid, 256>>>(x, Wz, Wf, Wo, bz, bf, bo);

    int nA = BB * NC * OO;              // 262144
    scan_passA<<<nA / 256, 256>>>();
    scan_passB<<<(BB * OO) / 256, 256>>>();   // 16 blocks
    scan_passC<<<nA / 256, 256>>>(out);
}

// round 17
// speedup vs baseline: 3.2368x; 3.2368x over previous
#include <cuda_runtime.h>
#include <cuda_fp16.h>
#include <math.h>
#include <stdint.h>

// ---------------- problem constants ----------------
#define BB 8
#define TT 4096
#define DD 512
#define OO 512
#define MM (BB*TT)          // 32768 tokens
#define KW 1024             // weight K (2*D)
#define KP2 2048            // augmented K' = [Ahi | Alo] x [Bhi ; Bhi]
#define BK 64               // K-chunk per stage (64 fp16 = 128B rows)
#define NCH2 (KP2/BK)       // 32
#define NC 64               // scan chunks
#define CL (TT/NC)          // 64

// ---------------- scratch (device globals) ----------------
__device__ __half g_xhi[(size_t)MM * DD];
__device__ __half g_xlo[(size_t)MM * DD];
__device__ __half g_bt[(size_t)3 * OO * KW];   // [gate][n][k] K-contiguous fp16
__device__ float g_z[(size_t)MM * OO];
__device__ float g_f[(size_t)MM * OO];
__device__ float g_o[(size_t)MM * OO];
__device__ float g_cH[BB * NC * OO];
__device__ float g_cP[BB * NC * OO];
__device__ float g_cIn[BB * NC * OO];

// ---------------- helpers ----------------
__device__ __forceinline__ uint32_t smem_u32(const void* p) {
    uint32_t a;
    asm("{ .reg .u64 t; cvta.to.shared.u64 t, %1; cvt.u32.u64 %0, t; }" : "=r"(a) : "l"(p));
    return a;
}
__device__ __forceinline__ uint32_t sw128(uint32_t o) { return o ^ ((o >> 3) & 0x70); }

__device__ __forceinline__ void cp_async16(uint32_t dst, const void* src, uint32_t srcsize) {
    asm volatile("cp.async.cg.shared.global [%0], [%1], 16, %2;"
                 :: "r"(dst), "l"(src), "r"(srcsize) : "memory");
}
#define CP_COMMIT() asm volatile("cp.async.commit_group;" ::: "memory")
#define CP_WAIT(n)  asm volatile("cp.async.wait_group %0;" :: "n"(n) : "memory")

__device__ __forceinline__ void ldm_x4(uint32_t* r, uint32_t addr) {
    asm volatile("ldmatrix.sync.aligned.m8n8.x4.shared.b16 {%0,%1,%2,%3}, [%4];"
                 : "=r"(r[0]), "=r"(r[1]), "=r"(r[2]), "=r"(r[3]) : "r"(addr));
}
__device__ __forceinline__ void mma_16816(float* d, const uint32_t* a, uint32_t b0, uint32_t b1) {
    asm volatile(
        "mma.sync.aligned.m16n8k16.row.col.f32.f16.f16.f32 "
        "{%0,%1,%2,%3}, {%4,%5,%6,%7}, {%8,%9}, {%0,%1,%2,%3};"
        : "+f"(d[0]), "+f"(d[1]), "+f"(d[2]), "+f"(d[3])
        : "r"(a[0]), "r"(a[1]), "r"(a[2]), "r"(a[3]), "r"(b0), "r"(b1));
}

// ---------------- conversion kernels ----------------
__global__ __launch_bounds__(256) void convert_x(const float* __restrict__ x) {
    size_t idx = (size_t)blockIdx.x * 256 + threadIdx.x;      // < MM*DD/4
    float4 v = ((const float4*)x)[idx];
    __half h0 = __float2half(v.x), h1 = __float2half(v.y);
    __half h2 = __float2half(v.z), h3 = __float2half(v.w);
    __half l0 = __float2half(v.x - __half2float(h0));
    __half l1 = __float2half(v.y - __half2float(h1));
    __half l2 = __float2half(v.z - __half2float(h2));
    __half l3 = __float2half(v.w - __half2float(h3));
    ((__half2*)g_xhi)[idx * 2 + 0] = __halves2half2(h0, h1);
    ((__half2*)g_xhi)[idx * 2 + 1] = __halves2half2(h2, h3);
    ((__half2*)g_xlo)[idx * 2 + 0] = __halves2half2(l0, l1);
    ((__half2*)g_xlo)[idx * 2 + 1] = __halves2half2(l2, l3);
}

// transpose-pack: g_bt[gate][n][k] = fp16(W[w][d][n]), k = w*512+d
__global__ __launch_bounds__(1024) void convert_w(
    const float* __restrict__ Wz, const float* __restrict__ Wf, const float* __restrict__ Wo) {
    __shared__ float s[32][33];
    int g = blockIdx.z;
    const float* __restrict__ W = (g == 0) ? Wz : (g == 1 ? Wf : Wo);
    int k_r = blockIdx.x * 32 + threadIdx.y;
    int n_r = blockIdx.y * 32 + threadIdx.x;
    int w = k_r >> 9, d = k_r & 511;
    s[threadIdx.y][threadIdx.x] = W[((size_t)w * DD + d) * OO + n_r];
    __syncthreads();
    int k_w = blockIdx.x * 32 + threadIdx.x;
    int n_w = blockIdx.y * 32 + threadIdx.y;
    g_bt[((size_t)g * OO + n_w) * KW + k_w] = __float2half(s[threadIdx.x][threadIdx.y]);
}

// ---------------- mma.sync GEMM + activation epilogue ----------------
// Block tile 128(M) x 128(N), BK=64, 8 warps (warp tile 64x32), double buffer.
// SMEM: As[2][128][64] fp16 (16KB/stage) + Bs[2][128][64] (16KB/stage) = 64KB.
#define A_ST 16384
#define OFF_BS 32768
#define GEMM_SMEM 65536

__global__ __launch_bounds__(256) void gemm_mma(
    const float* __restrict__ bz, const float* __restrict__ bf, const float* __restrict__ bo) {
    extern __shared__ char smem[];
    const uint32_t sb = smem_u32(smem);
    const int tid = threadIdx.x;
    const int wid = tid >> 5;
    const int lane = tid & 31;
    const int wm = wid & 1;            // 2 m-groups of 64
    const int wn = wid >> 1;           // 4 n-groups of 32

    const int m0 = blockIdx.x * 128;
    const int by = blockIdx.y;         // 0..11
    const int gate = by >> 2;
    const int nIn = (by & 3) * 128;    // col base within gate

    const __half* __restrict__ bt0 = g_bt + (size_t)(gate * OO + nIn) * KW;

    // ---- stage loader: A 128x64 + B 128x64 fp16, SW128 rows of 128B ----
    auto load_stage = [&](int c, int st) {
        const int kp = c * BK;                 // global k' 0..2047
        const __half* __restrict__ abuf = (kp < KW) ? g_xhi : g_xlo;
        const int ka = kp & (KW - 1);
        const uint32_t abase = sb + st * A_ST;
        #pragma unroll
        for (int it = 0; it < 4; it++) {
            int e = tid + it * 256;
            int row = e >> 3, c16 = e & 7;     // 8 fp16 per 16B
            int k = ka + c16 * 8;
            int half = k >> 9, kcol = k & 511;
            int gi = m0 + row;
            bool zf = (half == 0) && ((gi & (TT - 1)) == 0);
            const char* src = (const char*)(abuf + ((size_t)(gi + half - 1) * DD + kcol));
            if (zf) src = (const char*)abuf;
            cp_async16(abase + sw128(row * 128 + c16 * 16), src, zf ? 0u : 16u);
        }
        const uint32_t bbase = sb + OFF_BS + st * A_ST;
        #pragma unroll
        for (int it = 0; it < 4; it++) {
            int e = tid + it * 256;
            int row = e >> 3, c16 = e & 7;
            const char* src = (const char*)(bt0 + (size_t)row * KW + ka + c16 * 8);
            cp_async16(bbase + sw128(row * 128 + c16 * 16), src, 16u);
        }
        CP_COMMIT();
    };

    float acc[4][4][4];
    #pragma unroll
    for (int i = 0; i < 4; i++)
        #pragma unroll
        for (int j = 0; j < 4; j++)
            #pragma unroll
            for (int r = 0; r < 4; r++) acc[i][j][r] = 0.0f;

    load_stage(0, 0);

    for (int c = 0; c < NCH2; c++) {
        const int s = c & 1;
        if (c + 1 < NCH2) { load_stage(c + 1, s ^ 1); CP_WAIT(1); }
        else              { CP_WAIT(0); }
        __syncthreads();

        const uint32_t abase = sb + s * A_ST;
        const uint32_t bbase = sb + OFF_BS + s * A_ST;
        #pragma unroll
        for (int ks = 0; ks < 4; ks++) {
            uint32_t afr[4][4], bfr[2][4];
            const uint32_t koff = ks * 32 + (lane >> 4) * 16;
            #pragma unroll
            for (int mt = 0; mt < 4; mt++) {
                int row = wm * 64 + mt * 16 + (lane & 15);
                ldm_x4(afr[mt], abase + sw128(row * 128 + koff));
            }
            #pragma unroll
            for (int np = 0; np < 2; np++) {
                int row = wn * 32 + np * 16 + (lane & 15);
                ldm_x4(bfr[np], bbase + sw128(row * 128 + koff));
            }
            #pragma unroll
            for (int mt = 0; mt < 4; mt++)
                #pragma unroll
                for (int nt = 0; nt < 4; nt++) {
                    int np = nt >> 1, od = nt & 1;
                    mma_16816(acc[mt][nt], afr[mt], bfr[np][od], bfr[np][od + 2]);
                }
        }
        __syncthreads();
    }

    // ---- epilogue: bias + activation + store ----
    float* __restrict__ gout = (gate == 0) ? g_z : (gate == 1 ? g_f : g_o);
    const float* __restrict__ bias = (gate == 0) ? bz : (gate == 1 ? bf : bo);
    #pragma unroll
    for (int nt = 0; nt < 4; nt++) {
        int col = nIn + wn * 32 + nt * 8 + (lane & 3) * 2;
        float b0 = bias[col], b1 = bias[col + 1];
        #pragma unroll
        for (int mt = 0; mt < 4; mt++) {
            int row = m0 + wm * 64 + mt * 16 + (lane >> 2);
            #pragma unroll
            for (int h = 0; h < 2; h++) {
                float v0 = acc[mt][nt][h * 2 + 0] + b0;
                float v1 = acc[mt][nt][h * 2 + 1] + b1;
                float2 o2;
                if (gate == 0) { o2.x = tanhf(v0); o2.y = tanhf(v1); }
                else {
                    o2.x = 1.0f / (1.0f + __expf(-v0));
                    o2.y = 1.0f / (1.0f + __expf(-v1));
                }
                *(float2*)(gout + (size_t)(row + h * 8) * OO + col) = o2;
            }
        }
    }
}

// ---------------- scan (3-pass chunked) ----------------
__global__ __launch_bounds__(256) void scan_passA(void) {
    int g = blockIdx.x * blockDim.x + threadIdx.x;
    int c = g & 511, rest = g >> 9;
    int chunk = rest & (NC - 1), b = rest >> 6;
    int idx = ((b * TT + chunk * CL) * OO) + c;
    float h = 0.0f, P = 1.0f;
    #pragma unroll 4
    for (int t = 0; t < CL; t++) {
        float f = g_f[idx], z = g_z[idx];
        h = z + f * (h - z);
        P *= f;
        idx += OO;
    }
    int j = (b * NC + chunk) * OO + c;
    g_cH[j] = h; g_cP[j] = P;
}

__global__ __launch_bounds__(256) void scan_passB(void) {
    int g = blockIdx.x * blockDim.x + threadIdx.x;
    int c = g & 511, b = g >> 9;
    float H = 0.0f;
    for (int k = 0; k < NC; k++) {
        int j = (b * NC + k) * OO + c;
        g_cIn[j] = H;
        H = g_cP[j] * H + g_cH[j];
    }
}

__global__ __launch_bounds__(256) void scan_passC(float* __restrict__ out) {
    int g = blockIdx.x * blockDim.x + threadIdx.x;
    int c = g & 511, rest = g >> 9;
    int chunk = rest & (NC - 1), b = rest >> 6;
    float h = g_cIn[(b * NC + chunk) * OO + c];
    int idx = ((b * TT + chunk * CL) * OO) + c;
    #pragma unroll 4
    for (int t = 0; t < CL; t++) {
        float f = g_f[idx], z = g_z[idx];
        h = z + f * (h - z);
        out[idx] = g_o[idx] * h;
        idx += OO;
    }
}

// ---------------- launch ----------------
extern "C" void kernel_launch(void* const* d_in, const int* in_sizes, int n_in,
                              void* d_out, int out_size) {
    const float* x  = (const float*)d_in[0];
    const float* Wz = (const float*)d_in[1];
    const float* Wf = (const float*)d_in[2];
    const float* Wo = (const float*)d_in[3];
    const float* bz = (const float*)d_in[4];
    const float* bf = (const float*)d_in[5];
    const float* bo = (const float*)d_in[6];
    float* out = (float*)d_out;

    cudaFuncSetAttribute(gemm_mma, cudaFuncAttributeMaxDynamicSharedMemorySize, GEMM_SMEM);

    convert_x<<<(MM * DD / 4) / 256, 256>>>(x);
    convert_w<<<dim3(KW / 32, OO / 32, 3), dim3(32, 32)>>>(Wz, Wf, Wo);

    gemm_mma<<<dim3(MM / 128, 12), 256, GEMM_SMEM>>>(bz, bf, bo);

    int nA = BB * NC * OO;
    scan_passA<<<nA / 256, 256>>>();
    scan_passB<<<(BB * OO) / 256, 256>>>();
    scan_passC<<<nA / 256, 256>>>(out);
}